// round 3
// baseline (speedup 1.0000x reference)
#include <cuda_runtime.h>
#include <cuda_bf16.h>
#include <cstdint>

// ---------------- problem constants ----------------
#define NLAYERS 4
#define INSZ    80
#define DMODEL  512
#define NHEAD   8
#define DH      64
#define DFF     2048
#define BATCH   16
#define SMAX    512
#define NTOK    (BATCH * SMAX)   // 8192

typedef __nv_bfloat16 bf16;

// ---------------- scratch (device globals; no allocs allowed) ----------------
__device__ float g_h   [NTOK * DMODEL];        // hidden state fp32
__device__ float g_qkv [NTOK * 3 * DMODEL];    // qkv fp32 (attention input)
__device__ float g_pool[BATCH * 8 * DMODEL];   // pooling partials

// split activations (bf16 hi/lo planes)
__device__ bf16 g_h_hi [NTOK * DMODEL],  g_h_lo [NTOK * DMODEL];
__device__ bf16 g_ctx_hi[NTOK * DMODEL], g_ctx_lo[NTOK * DMODEL];
__device__ bf16 g_ff_hi[NTOK * DFF],     g_ff_lo[NTOK * DFF];

// split weights (bf16 hi/lo planes), layout identical to fp32 sources
__device__ bf16 g_wqkv_hi[NLAYERS * 3 * DMODEL * DMODEL], g_wqkv_lo[NLAYERS * 3 * DMODEL * DMODEL];
__device__ bf16 g_wo_hi  [NLAYERS * DMODEL * DMODEL],     g_wo_lo  [NLAYERS * DMODEL * DMODEL];
__device__ bf16 g_w1_hi  [NLAYERS * DFF * DMODEL],        g_w1_lo  [NLAYERS * DFF * DMODEL];
__device__ bf16 g_w2_hi  [NLAYERS * DMODEL * DFF],        g_w2_lo  [NLAYERS * DMODEL * DFF];

enum { EPI_NONE = 0, EPI_PE = 1, EPI_RELU = 2, EPI_RES = 3 };

// ---------------- helpers -----------------------------------------------------
__device__ __forceinline__ void mma16816(float* d, const uint32_t* a, const uint32_t* b) {
    asm volatile(
        "mma.sync.aligned.m16n8k16.row.col.f32.bf16.bf16.f32 "
        "{%0,%1,%2,%3},{%4,%5,%6,%7},{%8,%9},{%0,%1,%2,%3};\n"
        : "+f"(d[0]), "+f"(d[1]), "+f"(d[2]), "+f"(d[3])
        : "r"(a[0]), "r"(a[1]), "r"(a[2]), "r"(a[3]), "r"(b[0]), "r"(b[1]));
}

__device__ __forceinline__ uint32_t ld32bf(const bf16* p) {
    return *reinterpret_cast<const uint32_t*>(p);
}

__device__ __forceinline__ void split1(float v, bf16& h, bf16& l) {
    h = __float2bfloat16(v);
    l = __float2bfloat16(v - __bfloat162float(h));
}

__device__ __forceinline__ void split4(float4 v, bf16* dh, bf16* dl) {
    union { bf16 b[4]; uint2 u; } H, L;
    split1(v.x, H.b[0], L.b[0]);
    split1(v.y, H.b[1], L.b[1]);
    split1(v.z, H.b[2], L.b[2]);
    split1(v.w, H.b[3], L.b[3]);
    *reinterpret_cast<uint2*>(dh) = H.u;
    *reinterpret_cast<uint2*>(dl) = L.u;
}

__device__ __forceinline__ void cp16(uint32_t saddr, const void* g) {
    asm volatile("cp.async.cg.shared.global [%0], [%1], 16;\n" :: "r"(saddr), "l"(g));
}
__device__ __forceinline__ void cp_commit() {
    asm volatile("cp.async.commit_group;\n");
}
template <int N>
__device__ __forceinline__ void cp_wait() {
    asm volatile("cp.async.wait_group %0;\n" :: "n"(N));
}

// ---------------- weight / generic fp32 -> hi/lo split kernel ----------------
__global__ __launch_bounds__(256) void split_kernel(
    const float* __restrict__ src, bf16* __restrict__ hi, bf16* __restrict__ lo)
{
    const int i = (blockIdx.x * 256 + threadIdx.x) * 4;
    float4 v = *(const float4*)(src + i);
    split4(v, hi + i, lo + i);
}

// =============================================================================
// bf16 split-precision tensor-core GEMM, pre-split operands:
//   C[M,N] = (Ah+Al)[M,K] * (Bh+Bl)[N,K]^T + bias (+epilogue)
//   acc += Ah*Bh + Ah*Bl + Al*Bh  (fp32 accum)
// Tiles 128x128x32, 256 threads (2 CTAs/SM target), cp.async double buffer.
// =============================================================================
#define BK    32
#define LDSK  40                   // padded k-stride (elems); 80B row, conflict-free
#define PLE   (128 * LDSK)         // elems per plane  (10 KB)
#define BUFE  (4 * PLE)            // elems per buffer (40 KB)
#define GSMEM (2 * BUFE * 2)       // bytes: 80 KB

template <int EPI>
__global__ __launch_bounds__(256, 2) void bgemm_kernel(
    const bf16* __restrict__ Ah, const bf16* __restrict__ Al,
    const bf16* __restrict__ Bh, const bf16* __restrict__ Bl,
    const float* __restrict__ bias, const float* __restrict__ res,
    float* __restrict__ Cf, bf16* __restrict__ Chi, bf16* __restrict__ Clo,
    int M, int N, int K)
{
    extern __shared__ bf16 sm[];
    const uint32_t smbase = (uint32_t)__cvta_generic_to_shared(sm);

    const int tid = threadIdx.x;
    const int bm = blockIdx.y * 128;
    const int bn = blockIdx.x * 128;

    const int wid  = tid >> 5;
    const int wm   = wid & 1;       // 64-row half
    const int wn   = wid >> 1;      // 32-col quarter
    const int lane = tid & 31;
    const int g    = lane >> 2;
    const int tg   = lane & 3;

    float acc[4][4][4];
#pragma unroll
    for (int i = 0; i < 4; i++)
#pragma unroll
        for (int j = 0; j < 4; j++)
#pragma unroll
            for (int r = 0; r < 4; r++) acc[i][j][r] = 0.0f;

    const int nt = K / BK;

    // async tile loader: 2 chunks of 16B per plane per thread
    const int c0  = tid * 2;
    const int lrow = c0 >> 2;            // 0..127 (both chunks same row)
    const int lcol = (c0 & 3) * 8;       // elem col of chunk 0 (chunk 1 at +8)

#define LOAD_TILE(T, BUF)                                                        \
    {                                                                            \
        const int k0 = (T) * BK;                                                 \
        const size_t ga = (size_t)(bm + lrow) * K + k0 + lcol;                   \
        const size_t gb = (size_t)(bn + lrow) * K + k0 + lcol;                   \
        const uint32_t sa = smbase + 2 * ((BUF) * BUFE + lrow * LDSK + lcol);    \
        cp16(sa,                Ah + ga);                                        \
        cp16(sa + 16,           Ah + ga + 8);                                    \
        cp16(sa + 2 * PLE,      Al + ga);                                        \
        cp16(sa + 2 * PLE + 16, Al + ga + 8);                                    \
        cp16(sa + 4 * PLE,      Bh + gb);                                        \
        cp16(sa + 4 * PLE + 16, Bh + gb + 8);                                    \
        cp16(sa + 6 * PLE,      Bl + gb);                                        \
        cp16(sa + 6 * PLE + 16, Bl + gb + 8);                                    \
    }

    LOAD_TILE(0, 0);
    cp_commit();

    for (int t = 0; t < nt; t++) {
        if (t + 1 < nt) {
            LOAD_TILE(t + 1, (t + 1) & 1);
            cp_commit();
            cp_wait<1>();
        } else {
            cp_wait<0>();
        }
        __syncthreads();

        const bf16* buf = sm + (t & 1) * BUFE;
        const bf16* pAh = buf;
        const bf16* pAl = buf + PLE;
        const bf16* pBh = buf + 2 * PLE;
        const bf16* pBl = buf + 3 * PLE;

#pragma unroll
        for (int ks = 0; ks < 2; ks++) {
            const int kc = ks * 16 + 2 * tg;
            uint32_t af[4][4], bh[4][2], bl[4][2];
#pragma unroll
            for (int mi = 0; mi < 4; mi++) {
                const bf16* p = pAh + (wm * 64 + mi * 16 + g) * LDSK + kc;
                af[mi][0] = ld32bf(p);
                af[mi][1] = ld32bf(p + 8 * LDSK);
                af[mi][2] = ld32bf(p + 8);
                af[mi][3] = ld32bf(p + 8 * LDSK + 8);
            }
#pragma unroll
            for (int ni = 0; ni < 4; ni++) {
                const bf16* p = pBh + (wn * 32 + ni * 8 + g) * LDSK + kc;
                bh[ni][0] = ld32bf(p);
                bh[ni][1] = ld32bf(p + 8);
            }
#pragma unroll
            for (int mi = 0; mi < 4; mi++)
#pragma unroll
                for (int ni = 0; ni < 4; ni++)
                    mma16816(acc[mi][ni], af[mi], bh[ni]);

#pragma unroll
            for (int ni = 0; ni < 4; ni++) {
                const bf16* p = pBl + (wn * 32 + ni * 8 + g) * LDSK + kc;
                bl[ni][0] = ld32bf(p);
                bl[ni][1] = ld32bf(p + 8);
            }
#pragma unroll
            for (int mi = 0; mi < 4; mi++)
#pragma unroll
                for (int ni = 0; ni < 4; ni++)
                    mma16816(acc[mi][ni], af[mi], bl[ni]);

#pragma unroll
            for (int mi = 0; mi < 4; mi++) {
                const bf16* p = pAl + (wm * 64 + mi * 16 + g) * LDSK + kc;
                af[mi][0] = ld32bf(p);
                af[mi][1] = ld32bf(p + 8 * LDSK);
                af[mi][2] = ld32bf(p + 8);
                af[mi][3] = ld32bf(p + 8 * LDSK + 8);
            }
#pragma unroll
            for (int mi = 0; mi < 4; mi++)
#pragma unroll
                for (int ni = 0; ni < 4; ni++)
                    mma16816(acc[mi][ni], af[mi], bh[ni]);
        }
        __syncthreads();
    }
#undef LOAD_TILE

    // ---- epilogue ----
#pragma unroll
    for (int mi = 0; mi < 4; mi++) {
#pragma unroll
        for (int ni = 0; ni < 4; ni++) {
            const int m = bm + wm * 64 + mi * 16 + g;
            const int n = bn + wn * 32 + ni * 8 + tg * 2;
            const float b0 = bias[n], b1 = bias[n + 1];
#pragma unroll
            for (int h = 0; h < 2; h++) {
                const int mm = m + h * 8;
                float v0 = acc[mi][ni][h * 2 + 0] + b0;
                float v1 = acc[mi][ni][h * 2 + 1] + b1;
                const size_t ix = (size_t)mm * N + n;
                if (EPI == EPI_RELU) {
                    v0 = fmaxf(v0, 0.0f); v1 = fmaxf(v1, 0.0f);
                    bf16 h0, l0, h1, l1;
                    split1(v0, h0, l0); split1(v1, h1, l1);
                    Chi[ix] = h0; Chi[ix + 1] = h1;
                    Clo[ix] = l0; Clo[ix + 1] = l1;
                } else {
                    if (EPI == EPI_RES) { v0 += res[ix]; v1 += res[ix + 1]; }
                    Cf[ix] = v0; Cf[ix + 1] = v1;
                }
            }
        }
    }
}

// ---------------- fp32 SGEMM for embed (K=80) + PE + split output ------------
__global__ __launch_bounds__(256) void embed_kernel(
    const float* __restrict__ A, const float* __restrict__ B,
    const float* __restrict__ bias,
    float* __restrict__ C, bf16* __restrict__ Chi, bf16* __restrict__ Clo,
    int M, int N, int K)
{
    __shared__ float As[16][132];
    __shared__ float Bs[16][132];

    const int tid = threadIdx.x;
    const int bm = blockIdx.y * 128;
    const int bn = blockIdx.x * 128;

    const int lr = tid >> 2;
    const int lc = (tid & 3) * 4;
    const int ty = tid >> 4;
    const int tx = tid & 15;

    float acc[8][8];
#pragma unroll
    for (int i = 0; i < 8; i++)
#pragma unroll
        for (int j = 0; j < 8; j++) acc[i][j] = 0.0f;

    for (int k0 = 0; k0 < K; k0 += 16) {
#pragma unroll
        for (int p = 0; p < 2; p++) {
            const int row = lr + p * 64;
            float4 a = *(const float4*)(A + (size_t)(bm + row) * K + k0 + lc);
            float4 b = *(const float4*)(B + (size_t)(bn + row) * K + k0 + lc);
            As[lc + 0][row] = a.x; As[lc + 1][row] = a.y;
            As[lc + 2][row] = a.z; As[lc + 3][row] = a.w;
            Bs[lc + 0][row] = b.x; Bs[lc + 1][row] = b.y;
            Bs[lc + 2][row] = b.z; Bs[lc + 3][row] = b.w;
        }
        __syncthreads();
#pragma unroll
        for (int kk = 0; kk < 16; kk++) {
            float a[8], b[8];
            *(float4*)(a)     = *(const float4*)&As[kk][ty * 8];
            *(float4*)(a + 4) = *(const float4*)&As[kk][ty * 8 + 4];
            *(float4*)(b)     = *(const float4*)&Bs[kk][tx * 8];
            *(float4*)(b + 4) = *(const float4*)&Bs[kk][tx * 8 + 4];
#pragma unroll
            for (int i = 0; i < 8; i++)
#pragma unroll
                for (int j = 0; j < 8; j++)
                    acc[i][j] += a[i] * b[j];
        }
        __syncthreads();
    }

    const int m0 = bm + ty * 8;
    const int n0 = bn + tx * 8;
    float bv[8];
#pragma unroll
    for (int j = 0; j < 8; j++) bv[j] = bias[n0 + j];

#pragma unroll
    for (int i = 0; i < 8; i++) {
        const int m = m0 + i;
        const int s = m & (SMAX - 1);
#pragma unroll
        for (int j = 0; j < 8; j++) {
            const int n = n0 + j;
            float v = acc[i][j] + bv[j];
            const int de = n & ~1;
            float ang = (float)s * expf((float)de * (-9.210340371976184f / 512.0f));
            v += (n & 1) ? cosf(ang) : sinf(ang);
            const size_t ix = (size_t)m * N + n;
            C[ix] = v;
            bf16 hh, ll; split1(v, hh, ll);
            Chi[ix] = hh; Clo[ix] = ll;
        }
    }
}

// ---------------- fused attention (fp32), epilogue writes ctx splits ---------
#define AQ   32
#define SPAD 516
#define KPAD 68
#define ATTN_SMEM ((AQ * SPAD + AQ * KPAD + 64 * KPAD) * 4)

__global__ __launch_bounds__(256) void attn_kernel(
    const float* __restrict__ qkv, const int* __restrict__ lens,
    bf16* __restrict__ ctx_hi, bf16* __restrict__ ctx_lo)
{
    extern __shared__ float smem[];
    float* sS = smem;
    float* sQ = sS + AQ * SPAD;
    float* sKV = sQ + AQ * KPAD;

    const int qt = blockIdx.x;
    const int hd = blockIdx.y;
    const int b  = blockIdx.z;
    const int t  = threadIdx.x;
    const int len = lens[b];

    const float* base = qkv + (size_t)b * SMAX * (3 * DMODEL);

    {
        const int r = t >> 4;
        const int c = (t & 15) * 4;
#pragma unroll
        for (int p = 0; p < 2; p++) {
            const int q = r + p * 16;
            float4 v = *(const float4*)(base + (size_t)(qt * AQ + q) * (3 * DMODEL) + hd * DH + c);
            *(float4*)(sQ + q * KPAD + c) = v;
        }
    }

    const int wq = (t >> 5) * 4;
    const int lk = t & 31;

    for (int kt = 0; kt < 8; kt++) {
        __syncthreads();
        {
            const int r = t >> 4;
            const int c = (t & 15) * 4;
#pragma unroll
            for (int p = 0; p < 4; p++) {
                const int key = r + p * 16;
                float4 v = *(const float4*)(base + (size_t)(kt * 64 + key) * (3 * DMODEL)
                                            + DMODEL + hd * DH + c);
                sKV[(c + 0) * KPAD + key] = v.x;
                sKV[(c + 1) * KPAD + key] = v.y;
                sKV[(c + 2) * KPAD + key] = v.z;
                sKV[(c + 3) * KPAD + key] = v.w;
            }
        }
        __syncthreads();

        float acc[4][2] = {{0.f,0.f},{0.f,0.f},{0.f,0.f},{0.f,0.f}};
#pragma unroll 8
        for (int d = 0; d < 64; d++) {
            const float k0v = sKV[d * KPAD + lk * 2];
            const float k1v = sKV[d * KPAD + lk * 2 + 1];
#pragma unroll
            for (int i = 0; i < 4; i++) {
                const float qv = sQ[(wq + i) * KPAD + d];
                acc[i][0] += qv * k0v;
                acc[i][1] += qv * k1v;
            }
        }
#pragma unroll
        for (int i = 0; i < 4; i++)
#pragma unroll
            for (int j = 0; j < 2; j++) {
                const int kk = kt * 64 + lk * 2 + j;
                sS[(wq + i) * SPAD + kk] = (kk < len) ? acc[i][j] * 0.125f : -1e9f;
            }
    }
    __syncthreads();

    {
        const int w = t >> 5, lane = t & 31;
        for (int qi = w * 4; qi < w * 4 + 4; qi++) {
            float* row = sS + qi * SPAD;
            float m = -1e30f;
            for (int k = lane; k < SMAX; k += 32) m = fmaxf(m, row[k]);
#pragma unroll
            for (int o = 16; o; o >>= 1) m = fmaxf(m, __shfl_xor_sync(0xffffffffu, m, o));
            float sum = 0.0f;
            for (int k = lane; k < SMAX; k += 32) {
                float e = expf(row[k] - m);
                row[k] = e;
                sum += e;
            }
#pragma unroll
            for (int o = 16; o; o >>= 1) sum += __shfl_xor_sync(0xffffffffu, sum, o);
            const float inv = 1.0f / sum;
            for (int k = lane; k < SMAX; k += 32) row[k] *= inv;
        }
    }

    float o[4][2] = {{0.f,0.f},{0.f,0.f},{0.f,0.f},{0.f,0.f}};
    const int dv = lk * 2;
    for (int kt = 0; kt < 8; kt++) {
        __syncthreads();
        {
            const int r = t >> 4;
            const int c = (t & 15) * 4;
#pragma unroll
            for (int p = 0; p < 4; p++) {
                const int key = r + p * 16;
                float4 v = *(const float4*)(base + (size_t)(kt * 64 + key) * (3 * DMODEL)
                                            + 2 * DMODEL + hd * DH + c);
                *(float4*)(sKV + key * KPAD + c) = v;
            }
        }
        __syncthreads();
#pragma unroll 8
        for (int k = 0; k < 64; k++) {
            const float v0 = sKV[k * KPAD + dv];
            const float v1 = sKV[k * KPAD + dv + 1];
#pragma unroll
            for (int i = 0; i < 4; i++) {
                const float p = sS[(wq + i) * SPAD + kt * 64 + k];
                o[i][0] += p * v0;
                o[i][1] += p * v1;
            }
        }
    }
#pragma unroll
    for (int i = 0; i < 4; i++) {
        const int q = qt * AQ + wq + i;
        const size_t ix = ((size_t)b * SMAX + q) * DMODEL + hd * DH + dv;
        bf16 h0, l0, h1, l1;
        split1(o[i][0], h0, l0);
        split1(o[i][1], h1, l1);
        ctx_hi[ix] = h0; ctx_hi[ix + 1] = h1;
        ctx_lo[ix] = l0; ctx_lo[ix + 1] = l1;
    }
}

// ---------------- LayerNorm (in place) + split output ------------------------
__global__ __launch_bounds__(128) void ln_kernel(
    float* __restrict__ h, const float* __restrict__ g, const float* __restrict__ bta,
    bf16* __restrict__ hhi, bf16* __restrict__ hlo)
{
    __shared__ float red[8];
    const int row = blockIdx.x;
    const int t = threadIdx.x;
    float* p = h + (size_t)row * DMODEL + t * 4;
    float4 v = *(float4*)p;
    float s  = v.x + v.y + v.z + v.w;
    float ss = v.x * v.x + v.y * v.y + v.z * v.z + v.w * v.w;
#pragma unroll
    for (int o = 16; o; o >>= 1) {
        s  += __shfl_xor_sync(0xffffffffu, s, o);
        ss += __shfl_xor_sync(0xffffffffu, ss, o);
    }
    const int w = t >> 5;
    if ((t & 31) == 0) { red[w] = s; red[4 + w] = ss; }
    __syncthreads();
    s  = red[0] + red[1] + red[2] + red[3];
    ss = red[4] + red[5] + red[6] + red[7];
    const float mean = s * (1.0f / DMODEL);
    const float var  = ss * (1.0f / DMODEL) - mean * mean;
    const float rstd = rsqrtf(var + 1e-5f);
    float4 gg = *(const float4*)(g + t * 4);
    float4 bb = *(const float4*)(bta + t * 4);
    v.x = (v.x - mean) * rstd * gg.x + bb.x;
    v.y = (v.y - mean) * rstd * gg.y + bb.y;
    v.z = (v.z - mean) * rstd * gg.z + bb.z;
    v.w = (v.w - mean) * rstd * gg.w + bb.w;
    *(float4*)p = v;
    split4(v, hhi + (size_t)row * DMODEL + t * 4, hlo + (size_t)row * DMODEL + t * 4);
}

// ---------------- two-phase masked mean pooling ------------------------------
__global__ __launch_bounds__(128) void pool_part_kernel(
    const float* __restrict__ h, const int* __restrict__ lens, float* __restrict__ part)
{
    const int b = blockIdx.x;
    const int ch = blockIdx.y;
    const int d = threadIdx.x * 4;
    const int len = lens[b];
    const int t0 = ch * 64;
    int nt = len - t0;
    if (nt > 64) nt = 64;
    float4 s = {0.f, 0.f, 0.f, 0.f};
    for (int t = 0; t < nt; t++) {
        float4 v = *(const float4*)(h + ((size_t)b * SMAX + t0 + t) * DMODEL + d);
        s.x += v.x; s.y += v.y; s.z += v.z; s.w += v.w;
    }
    *(float4*)(part + (size_t)(b * 8 + ch) * DMODEL + d) = s;
}

__global__ __launch_bounds__(DMODEL) void pool_final_kernel(
    const float* __restrict__ part, const int* __restrict__ lens,
    float* __restrict__ out, int out_size)
{
    const int b = blockIdx.x;
    const int d = threadIdx.x;
    float s = 0.0f;
#pragma unroll
    for (int c = 0; c < 8; c++) s += part[(size_t)(b * 8 + c) * DMODEL + d];
    out[b * DMODEL + d] = s / (float)lens[b];
    if (d == 0 && out_size >= BATCH * DMODEL + BATCH)
        out[BATCH * DMODEL + b] = (float)lens[b];
}

// ---------------- launch ------------------------------------------------------
extern "C" void kernel_launch(void* const* d_in, const int* in_sizes, int n_in,
                              void* d_out, int out_size)
{
    (void)in_sizes; (void)n_in;
    const float* x     = (const float*)d_in[0];
    const int*   lens  = (const int*)  d_in[1];
    const float* We    = (const float*)d_in[2];
    const float* be    = (const float*)d_in[3];
    const float* Wqkv  = (const float*)d_in[4];
    const float* bqkv  = (const float*)d_in[5];
    const float* Wo    = (const float*)d_in[6];
    const float* bo    = (const float*)d_in[7];
    const float* ln1g  = (const float*)d_in[8];
    const float* ln1b  = (const float*)d_in[9];
    const float* W1    = (const float*)d_in[10];
    const float* b1    = (const float*)d_in[11];
    const float* W2    = (const float*)d_in[12];
    const float* b2    = (const float*)d_in[13];
    const float* ln2g  = (const float*)d_in[14];
    const float* ln2b  = (const float*)d_in[15];
    float* out = (float*)d_out;

    void *ph, *pqkv, *ppool;
    void *phh, *phl, *pch, *pcl, *pfh, *pfl;
    void *pwqh, *pwql, *pwoh, *pwol, *pw1h, *pw1l, *pw2h, *pw2l;
    cudaGetSymbolAddress(&ph,    g_h);
    cudaGetSymbolAddress(&pqkv,  g_qkv);
    cudaGetSymbolAddress(&ppool, g_pool);
    cudaGetSymbolAddress(&phh,   g_h_hi);   cudaGetSymbolAddress(&phl, g_h_lo);
    cudaGetSymbolAddress(&pch,   g_ctx_hi); cudaGetSymbolAddress(&pcl, g_ctx_lo);
    cudaGetSymbolAddress(&pfh,   g_ff_hi);  cudaGetSymbolAddress(&pfl, g_ff_lo);
    cudaGetSymbolAddress(&pwqh,  g_wqkv_hi); cudaGetSymbolAddress(&pwql, g_wqkv_lo);
    cudaGetSymbolAddress(&pwoh,  g_wo_hi);   cudaGetSymbolAddress(&pwol, g_wo_lo);
    cudaGetSymbolAddress(&pw1h,  g_w1_hi);   cudaGetSymbolAddress(&pw1l, g_w1_lo);
    cudaGetSymbolAddress(&pw2h,  g_w2_hi);   cudaGetSymbolAddress(&pw2l, g_w2_lo);

    float* h    = (float*)ph;
    float* qkv  = (float*)pqkv;
    float* pool = (float*)ppool;
    bf16 *h_hi = (bf16*)phh, *h_lo = (bf16*)phl;
    bf16 *c_hi = (bf16*)pch, *c_lo = (bf16*)pcl;
    bf16 *f_hi = (bf16*)pfh, *f_lo = (bf16*)pfl;
    bf16 *wq_hi = (bf16*)pwqh, *wq_lo = (bf16*)pwql;
    bf16 *wo_hi = (bf16*)pwoh, *wo_lo = (bf16*)pwol;
    bf16 *w1_hi = (bf16*)pw1h, *w1_lo = (bf16*)pw1l;
    bf16 *w2_hi = (bf16*)pw2h, *w2_lo = (bf16*)pw2l;

    cudaFuncSetAttribute(attn_kernel,
                         cudaFuncAttributeMaxDynamicSharedMemorySize, ATTN_SMEM);
    cudaFuncSetAttribute(bgemm_kernel<EPI_NONE>,
                         cudaFuncAttributeMaxDynamicSharedMemorySize, GSMEM);
    cudaFuncSetAttribute(bgemm_kernel<EPI_RELU>,
                         cudaFuncAttributeMaxDynamicSharedMemorySize, GSMEM);
    cudaFuncSetAttribute(bgemm_kernel<EPI_RES>,
                         cudaFuncAttributeMaxDynamicSharedMemorySize, GSMEM);

    // ---- weight splits (once per launch) ----
    split_kernel<<<NLAYERS * 3 * DMODEL * DMODEL / 1024, 256>>>(Wqkv, wq_hi, wq_lo);
    split_kernel<<<NLAYERS * DMODEL * DMODEL / 1024, 256>>>(Wo, wo_hi, wo_lo);
    split_kernel<<<NLAYERS * DFF * DMODEL / 1024, 256>>>(W1, w1_hi, w1_lo);
    split_kernel<<<NLAYERS * DMODEL * DFF / 1024, 256>>>(W2, w2_hi, w2_lo);

    // ---- embedding + positional encoding; writes h fp32 + splits ----
    embed_kernel<<<dim3(DMODEL / 128, NTOK / 128), 256>>>(
        x, We, be, h, h_hi, h_lo, NTOK, DMODEL, INSZ);

    for (int l = 0; l < NLAYERS; l++) {
        const bf16* wqh = wq_hi + (size_t)l * 3 * DMODEL * DMODEL;
        const bf16* wql = wq_lo + (size_t)l * 3 * DMODEL * DMODEL;
        const bf16* woh = wo_hi + (size_t)l * DMODEL * DMODEL;
        const bf16* wol = wo_lo + (size_t)l * DMODEL * DMODEL;
        const bf16* w1h = w1_hi + (size_t)l * DFF * DMODEL;
        const bf16* w1l = w1_lo + (size_t)l * DFF * DMODEL;
        const bf16* w2h = w2_hi + (size_t)l * DMODEL * DFF;
        const bf16* w2l = w2_lo + (size_t)l * DMODEL * DFF;
        const float* bq  = bqkv + (size_t)l * 3 * DMODEL;
        const float* bO  = bo   + (size_t)l * DMODEL;
        const float* bf1 = b1   + (size_t)l * DFF;
        const float* bf2 = b2   + (size_t)l * DMODEL;

        // qkv = h @ Wqkv^T + bqkv  (fp32 out)
        bgemm_kernel<EPI_NONE><<<dim3(3 * DMODEL / 128, NTOK / 128), 256, GSMEM>>>(
            h_hi, h_lo, wqh, wql, bq, nullptr, qkv, nullptr, nullptr,
            NTOK, 3 * DMODEL, DMODEL);

        // attention -> ctx splits
        attn_kernel<<<dim3(SMAX / AQ, NHEAD, BATCH), 256, ATTN_SMEM>>>(
            qkv, lens, c_hi, c_lo);

        // h = h + ctx @ Wo^T + bo  (fp32 out, in place)
        bgemm_kernel<EPI_RES><<<dim3(DMODEL / 128, NTOK / 128), 256, GSMEM>>>(
            c_hi, c_lo, woh, wol, bO, h, h, nullptr, nullptr,
            NTOK, DMODEL, DMODEL);
        ln_kernel<<<NTOK, 128>>>(h, ln1g + l * DMODEL, ln1b + l * DMODEL, h_hi, h_lo);

        // ff = relu(h @ W1^T + b1)  (split out)
        bgemm_kernel<EPI_RELU><<<dim3(DFF / 128, NTOK / 128), 256, GSMEM>>>(
            h_hi, h_lo, w1h, w1l, bf1, nullptr, nullptr, f_hi, f_lo,
            NTOK, DFF, DMODEL);
        // h = h + ff @ W2^T + b2  (fp32 out)
        bgemm_kernel<EPI_RES><<<dim3(DMODEL / 128, NTOK / 128), 256, GSMEM>>>(
            f_hi, f_lo, w2h, w2l, bf2, h, h, nullptr, nullptr,
            NTOK, DMODEL, DFF);
        ln_kernel<<<NTOK, 128>>>(h, ln2g + l * DMODEL, ln2b + l * DMODEL, h_hi, h_lo);
    }

    pool_part_kernel<<<dim3(BATCH, 8), 128>>>(h, lens, pool);
    pool_final_kernel<<<BATCH, DMODEL>>>(pool, lens, out, out_size);
}